// round 16
// baseline (speedup 1.0000x reference)
#include <cuda_runtime.h>
#include <cuda_bf16.h>
#include <math.h>
#include <stdint.h>

#define CB 2
#define CS 2048
#define CH 1024
#define CNH 16
#define CHD 64
#define CE 8
#define CD 1024
#define CT (CB*CS)

#define MB (1024ull*1024ull)

// ---------------- scratch layout ----------------
static constexpr size_t OFF_WQ_ATTN = 0;
static constexpr size_t OFF_WQ_GATE = 4*MB;
static constexpr size_t OFF_WQ_UP   = 12*MB;
static constexpr size_t OFF_WQ_DOWN = 20*MB;
static constexpr size_t OFF_WSCALE  = 28*MB;
static constexpr size_t OFF_PART    = 28*MB + 4096;
static constexpr size_t OFF_XQ1     = 29*MB;
static constexpr size_t OFF_A1S     = 33*MB;
static constexpr size_t OFF_QKV     = 34*MB;
static constexpr size_t OFF_HB      = 82*MB;
static constexpr size_t OFF_HQA     = 98*MB;
static constexpr size_t OFF_HSA     = 102*MB;
static constexpr size_t OFF_X2      = 103*MB;
static constexpr size_t OFF_XQ2     = 119*MB;
static constexpr size_t OFF_A2S     = 123*MB;
static constexpr size_t OFF_IDX     = 123*MB + 64*1024;
static constexpr size_t OFF_CNT     = 123*MB + 128*1024;
static constexpr size_t OFF_SEG     = 123*MB + 129*1024;
static constexpr size_t OFF_CUR     = 123*MB + 130*1024;
static constexpr size_t OFF_TBL2    = 123*MB + 132*1024;   // [0]=ntiles, pairs from [2]
static constexpr size_t OFF_TBL3    = 123*MB + 136*1024;
static constexpr size_t OFF_PERM    = 124*MB;
static constexpr size_t OFF_GB      = 125*MB;
static constexpr size_t OFF_UB      = 141*MB;
static constexpr size_t OFF_HQM     = 157*MB;
static constexpr size_t OFF_HSM     = 161*MB;
static constexpr size_t SCRATCH_BYTES = 162*MB;

__device__ __align__(256) unsigned char g_scratch[SCRATCH_BYTES];

// ---------------- reductions ----------------
__device__ __forceinline__ float blk_reduce_sum(float v, float* red) {
    int tid = threadIdx.x;
    red[tid] = v; __syncthreads();
    #pragma unroll
    for (int s = 128; s > 0; s >>= 1) {
        if (tid < s) red[tid] += red[tid + s];
        __syncthreads();
    }
    float r = red[0]; __syncthreads();
    return r;
}

__device__ __forceinline__ float blk_reduce_max(float v, float* red) {
    int tid = threadIdx.x;
    red[tid] = v; __syncthreads();
    #pragma unroll
    for (int s = 128; s > 0; s >>= 1) {
        if (tid < s) red[tid] = fmaxf(red[tid], red[tid + s]);
        __syncthreads();
    }
    float r = red[0]; __syncthreads();
    return r;
}

// ---------------- weight quantization (4x float4 ILP) ----------------
__device__ __forceinline__ float abs4(float4 v) {
    return fabsf(v.x) + fabsf(v.y) + fabsf(v.z) + fabsf(v.w);
}

__global__ void absmean_partial(const float* __restrict__ w, float* __restrict__ part, int len4) {
    __shared__ float red[256];
    const float4* p = (const float4*)w + (size_t)blockIdx.y * len4;
    int i = blockIdx.x * 1024 + threadIdx.x;
    float4 v0 = p[i], v1 = p[i + 256], v2 = p[i + 512], v3 = p[i + 768];
    float s = (abs4(v0) + abs4(v1)) + (abs4(v2) + abs4(v3));
    s = blk_reduce_sum(s, red);
    if (threadIdx.x == 0) part[(size_t)blockIdx.y * gridDim.x + blockIdx.x] = s;
}

__global__ void absmean4(const float* __restrict__ w0, const float* __restrict__ w1,
                         const float* __restrict__ w2, const float* __restrict__ w3,
                         float* __restrict__ part, int len4) {
    __shared__ float red[256];
    int sl = blockIdx.y;
    const float* p = sl == 0 ? w0 : sl == 1 ? w1 : sl == 2 ? w2 : w3;
    const float4* p4 = (const float4*)p;
    int i = blockIdx.x * 1024 + threadIdx.x;
    float4 v0 = p4[i], v1 = p4[i + 256], v2 = p4[i + 512], v3 = p4[i + 768];
    float s = (abs4(v0) + abs4(v1)) + (abs4(v2) + abs4(v3));
    s = blk_reduce_sum(s, red);
    if (threadIdx.x == 0) part[(size_t)sl * gridDim.x + blockIdx.x] = s;
}

__global__ void finalize_wscale(const float* __restrict__ part, float* __restrict__ wsc,
                                int i0, int n) {
    int i = i0 + threadIdx.x;
    if (threadIdx.x >= n) return;
    float s = 0.f;
    for (int j = 0; j < 256; j++) s += part[i * 256 + j];
    wsc[i] = fmaxf(s * (1.0f / (1024.f * 1024.f)), 1e-5f);
}

__device__ __forceinline__ char quant_tern(float v, float s) {
    float q = rintf(v * s);
    q = fminf(fmaxf(q, -1.f), 1.f);
    return (char)(int)q;
}

__device__ __forceinline__ char4 qt4(float4 v, float s) {
    char4 o;
    o.x = quant_tern(v.x, s); o.y = quant_tern(v.y, s);
    o.z = quant_tern(v.z, s); o.w = quant_tern(v.w, s);
    return o;
}

__global__ void quantize_w(const float* __restrict__ w, int8_t* __restrict__ wq,
                           const float* __restrict__ wsc, int widx0, int len4) {
    int slice = blockIdx.y;
    float s = 1.0f / wsc[widx0 + slice];
    const float4* p = (const float4*)w + (size_t)slice * len4;
    char4* q = (char4*)wq + (size_t)slice * len4;
    int i = blockIdx.x * 1024 + threadIdx.x;
    float4 v0 = p[i], v1 = p[i + 256], v2 = p[i + 512], v3 = p[i + 768];
    q[i] = qt4(v0, s); q[i + 256] = qt4(v1, s);
    q[i + 512] = qt4(v2, s); q[i + 768] = qt4(v3, s);
}

__global__ void quantizeF4(const float* __restrict__ w0, const float* __restrict__ w1,
                           const float* __restrict__ w2, const float* __restrict__ w3,
                           int8_t* __restrict__ wq, const float* __restrict__ part,
                           float* __restrict__ wsc, int len4) {
    __shared__ float red[256];
    int sl = blockIdx.y;
    int tid = threadIdx.x;
    float total = blk_reduce_sum(part[sl * 256 + tid], red);
    float mean = fmaxf(total * (1.0f / (1024.f * 1024.f)), 1e-5f);
    if (blockIdx.x == 0 && tid == 0) wsc[sl] = mean;
    float s = 1.0f / mean;
    const float* p = sl == 0 ? w0 : sl == 1 ? w1 : sl == 2 ? w2 : w3;
    const float4* p4 = (const float4*)p;
    char4* q = (char4*)wq + (size_t)sl * len4;
    int i = blockIdx.x * 1024 + tid;
    float4 v0 = p4[i], v1 = p4[i + 256], v2 = p4[i + 512], v3 = p4[i + 768];
    q[i] = qt4(v0, s); q[i + 256] = qt4(v1, s);
    q[i + 512] = qt4(v2, s); q[i + 768] = qt4(v3, s);
}

// ---------------- activation rmsnorm + quant ----------------
__global__ void rmsnorm_quant(const float* __restrict__ x, const float* __restrict__ lnw,
                              int8_t* __restrict__ xq, float* __restrict__ ainv) {
    __shared__ float red[256];
    __shared__ float xs[CH];
    int t = blockIdx.x, tid = threadIdx.x;
    const float* xr = x + (size_t)t * CH;
    float v[4]; float ss = 0.f;
    #pragma unroll
    for (int i = 0; i < 4; i++) { v[i] = xr[tid + i * 256]; ss += v[i] * v[i]; }
    ss = blk_reduce_sum(ss, red);
    float r = rsqrtf(ss * (1.0f / CH) + 1e-5f);
    float amax = 0.f;
    #pragma unroll
    for (int i = 0; i < 4; i++) {
        float xn = v[i] * r * lnw[tid + i * 256];
        xs[tid + i * 256] = xn;
        amax = fmaxf(amax, fabsf(xn));
    }
    amax = blk_reduce_max(amax, red);
    float m = fmaxf(amax, 1e-5f);
    float s = 127.f / m;
    #pragma unroll
    for (int i = 0; i < 4; i++) {
        float qv = fminf(fmaxf(rintf(xs[tid + i * 256] * s), -128.f), 127.f);
        xq[(size_t)t * CH + tid + i * 256] = (int8_t)(int)qv;
    }
    if (tid == 0) ainv[t] = m * (1.0f / 127.f);
}

__global__ void act_quant_rows(const float* __restrict__ x, int8_t* __restrict__ xq,
                               float* __restrict__ ainv) {
    __shared__ float red[256];
    int t = blockIdx.x, tid = threadIdx.x;
    const float* xr = x + (size_t)t * CH;
    float v[4]; float amax = 0.f;
    #pragma unroll
    for (int i = 0; i < 4; i++) { v[i] = xr[tid + i * 256]; amax = fmaxf(amax, fabsf(v[i])); }
    amax = blk_reduce_max(amax, red);
    float m = fmaxf(amax, 1e-5f);
    float s = 127.f / m;
    #pragma unroll
    for (int i = 0; i < 4; i++) {
        float qv = fminf(fmaxf(rintf(v[i] * s), -128.f), 127.f);
        xq[(size_t)t * CH + tid + i * 256] = (int8_t)(int)qv;
    }
    if (tid == 0) ainv[t] = m * (1.0f / 127.f);
}

__global__ void rmsnorm2_router(const float* __restrict__ x, const float* __restrict__ lnw,
                                const float* __restrict__ rw, int8_t* __restrict__ xq,
                                float* __restrict__ ainv, int* __restrict__ idx,
                                int* __restrict__ counts) {
    __shared__ float red[256];
    __shared__ float xs[CH];
    __shared__ float logits[CE];
    int t = blockIdx.x, tid = threadIdx.x;
    const float* xr = x + (size_t)t * CH;
    float v[4]; float ss = 0.f;
    #pragma unroll
    for (int i = 0; i < 4; i++) { v[i] = xr[tid + i * 256]; ss += v[i] * v[i]; }
    ss = blk_reduce_sum(ss, red);
    float r = rsqrtf(ss * (1.0f / CH) + 1e-5f);
    float amax = 0.f;
    #pragma unroll
    for (int i = 0; i < 4; i++) {
        float xn = v[i] * r * lnw[tid + i * 256];
        xs[tid + i * 256] = xn;
        amax = fmaxf(amax, fabsf(xn));
    }
    amax = blk_reduce_max(amax, red);
    float m = fmaxf(amax, 1e-5f);
    float s = 127.f / m;
    #pragma unroll
    for (int i = 0; i < 4; i++) {
        float qv = fminf(fmaxf(rintf(xs[tid + i * 256] * s), -128.f), 127.f);
        xq[(size_t)t * CH + tid + i * 256] = (int8_t)(int)qv;
    }
    if (tid == 0) ainv[t] = m * (1.0f / 127.f);
    __syncthreads();

    int w = tid >> 5, lane = tid & 31;
    float acc = 0.f;
    for (int h = lane; h < CH; h += 32) acc += xs[h] * rw[w * CH + h];
    #pragma unroll
    for (int o = 16; o > 0; o >>= 1) acc += __shfl_down_sync(0xffffffffu, acc, o);
    if (lane == 0) logits[w] = acc;
    __syncthreads();
    if (tid == 0) {
        float best = logits[0]; int bi = 0;
        #pragma unroll
        for (int e = 1; e < CE; e++) if (logits[e] > best) { best = logits[e]; bi = e; }
        idx[t] = bi;
        atomicAdd(&counts[bi], 1);
    }
}

__global__ void zero_ints(int* __restrict__ counts, int* __restrict__ cursor) {
    if (threadIdx.x < CE) { counts[threadIdx.x] = 0; cursor[threadIdx.x] = 0; }
}

// build segment offsets AND compact tile tables for the MoE GEMMs
__global__ void build_offsets(const int* __restrict__ counts, int* __restrict__ seg,
                              int* __restrict__ tbl2, int* __restrict__ tbl3) {
    if (threadIdx.x == 0) {
        int a = 0;
        for (int e = 0; e < CE; e++) { seg[e] = a; a += counts[e]; }
        seg[CE] = a;
        // gate/up tiles: z in [0,16), expert = z&7
        int n2 = 0;
        for (int z = 0; z < 16; z++) {
            int c = counts[z & 7];
            for (int m0 = 0; m0 < c; m0 += 128) {
                tbl2[2 + 2 * n2] = z;
                tbl2[3 + 2 * n2] = m0;
                n2++;
            }
        }
        tbl2[0] = n2;
        // down tiles: z in [0,8)
        int n3 = 0;
        for (int z = 0; z < CE; z++) {
            int c = counts[z];
            for (int m0 = 0; m0 < c; m0 += 128) {
                tbl3[2 + 2 * n3] = z;
                tbl3[3 + 2 * n3] = m0;
                n3++;
            }
        }
        tbl3[0] = n3;
    }
}

__global__ void scatter_tokens(const int* __restrict__ idx, const int* __restrict__ seg,
                               int* __restrict__ cursor, int* __restrict__ perm) {
    int t = blockIdx.x * 256 + threadIdx.x;
    if (t >= CT) return;
    int e = idx[t];
    int p = atomicAdd(&cursor[e], 1);
    perm[seg[e] + p] = t;
}

// ---------------- int8 x ternary GEMM: mma.sync + ldmatrix + cp.async (3-stage) ----------------
__device__ __forceinline__ void mma_s8(int* c, const int* a, const int* b) {
    asm volatile(
        "mma.sync.aligned.m16n8k32.row.col.s32.s8.s8.s32 "
        "{%0,%1,%2,%3}, {%4,%5,%6,%7}, {%8,%9}, {%0,%1,%2,%3};"
        : "+r"(c[0]), "+r"(c[1]), "+r"(c[2]), "+r"(c[3])
        : "r"(a[0]), "r"(a[1]), "r"(a[2]), "r"(a[3]), "r"(b[0]), "r"(b[1]));
}

#define LDMX4(r, addr) \
    asm volatile("ldmatrix.sync.aligned.m8n8.x4.shared.b16 {%0,%1,%2,%3}, [%4];" \
        : "=r"((r)[0]), "=r"((r)[1]), "=r"((r)[2]), "=r"((r)[3]) : "r"(addr))

#define CPA16(dst, src) \
    asm volatile("cp.async.cg.shared.global [%0], [%1], 16;" :: "r"(dst), "l"(src))
#define CPCOMMIT() asm volatile("cp.async.commit_group;" ::: "memory")

static constexpr int A_STG = 128 * 80;
static constexpr int B_STG = 64 * 80;

template<int MODE>
__global__ void __launch_bounds__(256) gemm_mma(
        const int8_t* __restrict__ A, const int8_t* __restrict__ Bw,
        float* __restrict__ Out, __nv_bfloat16* __restrict__ OutB,
        const float* __restrict__ ascale,
        const float* __restrict__ wscale,
        const float* __restrict__ resid,
        const int* __restrict__ perm,
        const int* __restrict__ seg,
        const int* __restrict__ tbl) {
    int n0 = blockIdx.x * 64;
    int m0, z;
    int off = 0, cnt = CT;
    if (MODE >= 2) {
        int nt = tbl[0];
        if ((int)blockIdx.y >= nt) return;
        z = tbl[2 + 2 * blockIdx.y];
        m0 = tbl[3 + 2 * blockIdx.y];
        int e = (MODE == 2) ? (z & 7) : z;
        off = seg[e];
        cnt = seg[e + 1] - off;
    } else {
        m0 = blockIdx.y * 128;
        z = blockIdx.z;
    }

    const int8_t* Bz = Bw;
    if (MODE == 0) Bz = Bw + (size_t)z * (CH * CH);
    if (MODE >= 2) Bz = Bw + (size_t)z * ((size_t)CD * CH);
    const int8_t* brow0 = Bz + (size_t)n0 * 1024;

    __shared__ __align__(16) int8_t As[3][128][80];
    __shared__ __align__(16) int8_t Bs[3][64][80];
    __shared__ const int8_t* aptr[128];
    __shared__ float rowsc[128];
    __shared__ int dstrow[128];

    int tid = threadIdx.x;
    if (tid < 128) {
        int r = m0 + tid;
        if (MODE <= 1) {
            aptr[tid] = A + (size_t)r * 1024;
            rowsc[tid] = ascale[r];
        } else if (MODE == 2) {
            int rr = r < cnt - 1 ? r : cnt - 1;
            int tok = perm[off + rr];
            aptr[tid] = A + (size_t)tok * 1024;
            rowsc[tid] = ascale[tok];
            dstrow[tid] = off + r;
        } else {
            int rr = r < cnt - 1 ? r : cnt - 1;
            aptr[tid] = A + (size_t)(off + rr) * 1024;
            rowsc[tid] = ascale[off + rr];
            dstrow[tid] = perm[off + rr];
        }
    }
    __syncthreads();

    int ar = tid >> 1, ao = (tid & 1) * 32;
    int brr = tid >> 2, bo = (tid & 3) * 16;
    const int8_t* pA = aptr[ar];
    const int8_t* pB = brow0 + (size_t)brr * 1024;

    uint32_t As_u = (uint32_t)__cvta_generic_to_shared(&As[0][0][0]);
    uint32_t Bs_u = (uint32_t)__cvta_generic_to_shared(&Bs[0][0][0]);
    uint32_t aSt = As_u + ar * 80 + ao;
    uint32_t bSt = Bs_u + brr * 80 + bo;

    int w = tid >> 5, lane = tid & 31;
    int warpM = w & 3, warpN = w >> 2;
    int gid = lane >> 2, tig = lane & 3;

    int rowA_ld = warpM * 32 + (lane & 7) + ((lane >> 3) & 1) * 8;
    uint32_t aF = As_u + rowA_ld * 80 + (lane >> 4) * 16;
    int rowB_ld = warpN * 32 + (lane & 7) + (lane >> 4) * 8;
    uint32_t bF = Bs_u + rowB_ld * 80 + ((lane >> 3) & 1) * 16;

    int c[2][4][4];
    #pragma unroll
    for (int i = 0; i < 2; i++)
        #pragma unroll
        for (int j = 0; j < 4; j++)
            #pragma unroll
            for (int k = 0; k < 4; k++) c[i][j][k] = 0;

    #pragma unroll
    for (int s = 0; s < 2; s++) {
        uint32_t aD = aSt + s * A_STG;
        CPA16(aD, pA + s * 64 + ao);
        CPA16(aD + 16, pA + s * 64 + ao + 16);
        CPA16(bSt + s * B_STG, pB + s * 64 + bo);
        CPCOMMIT();
    }

    #pragma unroll 1
    for (int kt = 0; kt < 16; kt++) {
        if (kt < 15) {
            asm volatile("cp.async.wait_group 1;" ::: "memory");
        } else {
            asm volatile("cp.async.wait_group 0;" ::: "memory");
        }
        __syncthreads();
        if (kt < 14) {
            int s = kt + 2;
            int b = s % 3;
            uint32_t aD = aSt + b * A_STG;
            CPA16(aD, pA + s * 64 + ao);
            CPA16(aD + 16, pA + s * 64 + ao + 16);
            CPA16(bSt + b * B_STG, pB + s * 64 + bo);
            CPCOMMIT();
        }
        int stg = kt % 3;
        uint32_t aBase = aF + stg * A_STG;
        uint32_t bBase = bF + stg * B_STG;
        #pragma unroll
        for (int ks = 0; ks < 2; ks++) {
            int a0[4], a1[4], b01[4], b23[4];
            LDMX4(a0, aBase + ks * 32);
            LDMX4(a1, aBase + 16 * 80 + ks * 32);
            LDMX4(b01, bBase + ks * 32);
            LDMX4(b23, bBase + 16 * 80 + ks * 32);
            mma_s8(c[0][0], a0, b01 + 0);
            mma_s8(c[0][1], a0, b01 + 2);
            mma_s8(c[0][2], a0, b23 + 0);
            mma_s8(c[0][3], a0, b23 + 2);
            mma_s8(c[1][0], a1, b01 + 0);
            mma_s8(c[1][1], a1, b01 + 2);
            mma_s8(c[1][2], a1, b23 + 0);
            mma_s8(c[1][3], a1, b23 + 2);
        }
    }

    float wS = wscale[(MODE == 0 || MODE >= 2) ? z : 0];

    #pragma unroll
    for (int wm = 0; wm < 2; wm++) {
        int r0 = warpM * 32 + wm * 16 + gid;
        int r1 = r0 + 8;
        float av0 = rowsc[r0] * wS;
        float av1 = rowsc[r1] * wS;
        #pragma unroll
        for (int nt = 0; nt < 4; nt++) {
            int colL = warpN * 32 + nt * 8 + tig * 2;
            int* cc = c[wm][nt];
            if (MODE == 0) {
                int nh = n0 >> 6;
                int gr0 = m0 + r0, gr1 = m0 + r1;
                int b0 = gr0 / CS, sr0 = gr0 % CS;
                int b1 = gr1 / CS, sr1 = gr1 % CS;
                __nv_bfloat16* base = OutB + (size_t)z * ((size_t)CT * CH);
                __nv_bfloat162 o0 = {__float2bfloat16(cc[0] * av0), __float2bfloat16(cc[1] * av0)};
                __nv_bfloat162 o1 = {__float2bfloat16(cc[2] * av1), __float2bfloat16(cc[3] * av1)};
                *(__nv_bfloat162*)(base + (((size_t)b0 * CNH + nh) * CS + sr0) * CHD + colL) = o0;
                *(__nv_bfloat162*)(base + (((size_t)b1 * CNH + nh) * CS + sr1) * CHD + colL) = o1;
            } else if (MODE == 1) {
                size_t rb0 = (size_t)(m0 + r0) * CH + n0 + colL;
                size_t rb1 = (size_t)(m0 + r1) * CH + n0 + colL;
                float2 rv0 = *(const float2*)(resid + rb0);
                float2 rv1 = *(const float2*)(resid + rb1);
                float2 o0 = {rv0.x + cc[0] * av0, rv0.y + cc[1] * av0};
                float2 o1 = {rv1.x + cc[2] * av1, rv1.y + cc[3] * av1};
                *(float2*)(Out + rb0) = o0;
                *(float2*)(Out + rb1) = o1;
            } else if (MODE == 2) {
                size_t half = (size_t)(z >> 3) * ((size_t)CT * CD);
                if (m0 + r0 < cnt) {
                    size_t rb = half + (size_t)dstrow[r0] * CD + n0 + colL;
                    float2 o = {cc[0] * av0, cc[1] * av0};
                    *(float2*)(Out + rb) = o;
                }
                if (m0 + r1 < cnt) {
                    size_t rb = half + (size_t)dstrow[r1] * CD + n0 + colL;
                    float2 o = {cc[2] * av1, cc[3] * av1};
                    *(float2*)(Out + rb) = o;
                }
            } else {
                if (m0 + r0 < cnt) {
                    size_t rb = (size_t)dstrow[r0] * CH + n0 + colL;
                    float2 rv = *(const float2*)(resid + rb);
                    float2 o = {rv.x + cc[0] * av0, rv.y + cc[1] * av0};
                    *(float2*)(Out + rb) = o;
                }
                if (m0 + r1 < cnt) {
                    size_t rb = (size_t)dstrow[r1] * CH + n0 + colL;
                    float2 rv = *(const float2*)(resid + rb);
                    float2 o = {rv.x + cc[2] * av1, rv.y + cc[3] * av1};
                    *(float2*)(Out + rb) = o;
                }
            }
        }
    }
}

// ---------------- attention: FA2-style, causal-balanced, cp.async double-buffered K/V ----------------
__device__ __forceinline__ void mma_bf16(float* c, const uint32_t* a, uint32_t b0, uint32_t b1) {
    asm volatile(
        "mma.sync.aligned.m16n8k16.row.col.f32.bf16.bf16.f32 "
        "{%0,%1,%2,%3}, {%4,%5,%6,%7}, {%8,%9}, {%0,%1,%2,%3};"
        : "+f"(c[0]), "+f"(c[1]), "+f"(c[2]), "+f"(c[3])
        : "r"(a[0]), "r"(a[1]), "r"(a[2]), "r"(a[3]), "r"(b0), "r"(b1));
}

__device__ __forceinline__ void ldmx4t(uint32_t& r0, uint32_t& r1, uint32_t& r2, uint32_t& r3,
                                       uint32_t addr) {
    asm volatile("ldmatrix.sync.aligned.m8n8.x4.trans.shared.b16 {%0,%1,%2,%3}, [%4];"
        : "=r"(r0), "=r"(r1), "=r"(r2), "=r"(r3) : "r"(addr));
}

__device__ __forceinline__ uint32_t pack_bf2(float a, float b) {
    __nv_bfloat162 t = __floats2bfloat162_rn(a, b);
    return *(uint32_t*)&t;
}

static constexpr int KLD = 72;
#define ASCL 0.18033688011112042f   // 0.125 * log2(e)

__global__ void __launch_bounds__(128) attn_fa2(
        const __nv_bfloat16* __restrict__ Qg, const __nv_bfloat16* __restrict__ Kg,
        const __nv_bfloat16* __restrict__ Vg, float* __restrict__ Hout) {
    __shared__ __align__(16) __nv_bfloat16 Ks[2][64][KLD];
    __shared__ __align__(16) __nv_bfloat16 Vs[2][64][KLD];

    int bh = blockIdx.y;
    const __nv_bfloat16* Qb = Qg + (size_t)bh * CS * CHD;
    const __nv_bfloat16* Kb = Kg + (size_t)bh * CS * CHD;
    const __nv_bfloat16* Vb = Vg + (size_t)bh * CS * CHD;

    int tid = threadIdx.x;
    int w = tid >> 5, lane = tid & 31;
    int gid = lane >> 2, tig = lane & 3;

    int b = bh / CNH, nh = bh % CNH;

    int lrow[4], lcol[4];
    #pragma unroll
    for (int u = 0; u < 4; u++) {
        int i = tid + u * 128;
        lrow[u] = i >> 3;
        lcol[u] = (i & 7) * 8;
    }

    #pragma unroll 1
    for (int rep = 0; rep < 2; rep++) {
        int qb = rep == 0 ? (31 - (int)blockIdx.x) : (int)blockIdx.x;
        int q0 = qb * 64;
        int qr0 = q0 + w * 16 + gid;
        int qr1 = qr0 + 8;

        uint32_t qf[4][4];
        #pragma unroll
        for (int k = 0; k < 4; k++) {
            const __nv_bfloat16* p0 = Qb + (size_t)qr0 * CHD + k * 16 + 2 * tig;
            const __nv_bfloat16* p1 = Qb + (size_t)qr1 * CHD + k * 16 + 2 * tig;
            qf[k][0] = *(const uint32_t*)p0;
            qf[k][1] = *(const uint32_t*)p1;
            qf[k][2] = *(const uint32_t*)(p0 + 8);
            qf[k][3] = *(const uint32_t*)(p1 + 8);
        }

        float o[8][4];
        #pragma unroll
        for (int nt = 0; nt < 8; nt++)
            #pragma unroll
            for (int j = 0; j < 4; j++) o[nt][j] = 0.f;
        float m0 = -INFINITY, m1 = -INFINITY, l0 = 0.f, l1 = 0.f;

        int nkt = qb + 1;

        __syncthreads();
        #pragma unroll
        for (int u = 0; u < 4; u++) {
            CPA16((uint32_t)__cvta_generic_to_shared(&Ks[0][lrow[u]][lcol[u]]),
                  Kb + (size_t)lrow[u] * CHD + lcol[u]);
            CPA16((uint32_t)__cvta_generic_to_shared(&Vs[0][lrow[u]][lcol[u]]),
                  Vb + (size_t)lrow[u] * CHD + lcol[u]);
        }
        CPCOMMIT();

        #pragma unroll 1
        for (int kt = 0; kt < nkt; kt++) {
            int buf = kt & 1;
            asm volatile("cp.async.wait_group 0;" ::: "memory");
            __syncthreads();
            if (kt + 1 < nkt) {
                int k0n = (kt + 1) * 64;
                int nb = buf ^ 1;
                #pragma unroll
                for (int u = 0; u < 4; u++) {
                    CPA16((uint32_t)__cvta_generic_to_shared(&Ks[nb][lrow[u]][lcol[u]]),
                          Kb + (size_t)(k0n + lrow[u]) * CHD + lcol[u]);
                    CPA16((uint32_t)__cvta_generic_to_shared(&Vs[nb][lrow[u]][lcol[u]]),
                          Vb + (size_t)(k0n + lrow[u]) * CHD + lcol[u]);
                }
                CPCOMMIT();
            }
            int k0 = kt * 64;

            float s[8][4];
            #pragma unroll
            for (int nt = 0; nt < 8; nt++)
                #pragma unroll
                for (int j = 0; j < 4; j++) s[nt][j] = 0.f;
            #pragma unroll
            for (int k = 0; k < 4; k++) {
                #pragma unroll
                for (int nt = 0; nt < 8; nt++) {
                    uint32_t b0 = *(const uint32_t*)&Ks[buf][nt * 8 + gid][k * 16 + 2 * tig];
                    uint32_t b1 = *(const uint32_t*)&Ks[buf][nt * 8 + gid][k * 16 + 8 + 2 * tig];
                    mma_bf16(s[nt], qf[k], b0, b1);
                }
            }

            bool diag = (kt == qb);
            float rmax0 = -INFINITY, rmax1 = -INFINITY;
            #pragma unroll
            for (int nt = 0; nt < 8; nt++) {
                int cg = k0 + nt * 8 + 2 * tig;
                #pragma unroll
                for (int j = 0; j < 2; j++) {
                    float v0 = s[nt][j] * ASCL;
                    float v1 = s[nt][2 + j] * ASCL;
                    if (diag && cg + j > qr0) v0 = -INFINITY;
                    if (diag && cg + j > qr1) v1 = -INFINITY;
                    s[nt][j] = v0; s[nt][2 + j] = v1;
                    rmax0 = fmaxf(rmax0, v0); rmax1 = fmaxf(rmax1, v1);
                }
            }
            rmax0 = fmaxf(rmax0, __shfl_xor_sync(0xffffffffu, rmax0, 1));
            rmax0 = fmaxf(rmax0, __shfl_xor_sync(0xffffffffu, rmax0, 2));
            rmax1 = fmaxf(rmax1, __shfl_xor_sync(0xffffffffu, rmax1, 1));
            rmax1 = fmaxf(rmax1, __shfl_xor_sync(0xffffffffu, rmax1, 2));

            float mn0 = fmaxf(m0, rmax0), mn1 = fmaxf(m1, rmax1);
            float sum0 = 0.f, sum1 = 0.f;
            #pragma unroll
            for (int nt = 0; nt < 8; nt++) {
                s[nt][0] = exp2f(s[nt][0] - mn0);
                s[nt][1] = exp2f(s[nt][1] - mn0);
                s[nt][2] = exp2f(s[nt][2] - mn1);
                s[nt][3] = exp2f(s[nt][3] - mn1);
                sum0 += s[nt][0] + s[nt][1];
                sum1 += s[nt][2] + s[nt][3];
            }
            sum0 += __shfl_xor_sync(0xffffffffu, sum0, 1);
            sum0 += __shfl_xor_sync(0xffffffffu, sum0, 2);
            sum1 += __shfl_xor_sync(0xffffffffu, sum1, 1);
            sum1 += __shfl_xor_sync(0xffffffffu, sum1, 2);

            float rs0 = exp2f(m0 - mn0), rs1 = exp2f(m1 - mn1);
            m0 = mn0; m1 = mn1;
            l0 = l0 * rs0 + sum0;
            l1 = l1 * rs1 + sum1;
            #pragma unroll
            for (int nt = 0; nt < 8; nt++) {
                o[nt][0] *= rs0; o[nt][1] *= rs0;
                o[nt][2] *= rs1; o[nt][3] *= rs1;
            }

            #pragma unroll
            for (int kb = 0; kb < 4; kb++) {
                uint32_t pf[4];
                pf[0] = pack_bf2(s[2 * kb][0], s[2 * kb][1]);
                pf[1] = pack_bf2(s[2 * kb][2], s[2 * kb][3]);
                pf[2] = pack_bf2(s[2 * kb + 1][0], s[2 * kb + 1][1]);
                pf[3] = pack_bf2(s[2 * kb + 1][2], s[2 * kb + 1][3]);
                #pragma unroll
                for (int nb = 0; nb < 4; nb++) {
                    uint32_t v0, v1, v2, v3;
                    uint32_t addr = (uint32_t)__cvta_generic_to_shared(
                        &Vs[buf][kb * 16 + (lane & 15)][nb * 16 + ((lane >> 4) << 3)]);
                    ldmx4t(v0, v1, v2, v3, addr);
                    mma_bf16(o[2 * nb], pf, v0, v1);
                    mma_bf16(o[2 * nb + 1], pf, v2, v3);
                }
            }
        }

        float inv0 = 1.0f / l0, inv1 = 1.0f / l1;
        #pragma unroll
        for (int nt = 0; nt < 8; nt++) {
            int col = nt * 8 + 2 * tig;
            float2 w0v = {o[nt][0] * inv0, o[nt][1] * inv0};
            float2 w1v = {o[nt][2] * inv1, o[nt][3] * inv1};
            *(float2*)(Hout + (((size_t)b * CS + qr0) * CNH + nh) * CHD + col) = w0v;
            *(float2*)(Hout + (((size_t)b * CS + qr1) * CNH + nh) * CHD + col) = w1v;
        }
    }
}

// ---------------- MoE elementwise: hh = relu(g)^2 * u, then act_quant ----------------
__global__ void hh_quant(const float* __restrict__ g, const float* __restrict__ u,
                         int8_t* __restrict__ hq, float* __restrict__ hs) {
    __shared__ float red[256];
    __shared__ float hb[CD];
    int slot = blockIdx.x, tid = threadIdx.x;
    float amax = 0.f;
    #pragma unroll
    for (int i = 0; i < 4; i++) {
        int k = tid + i * 256;
        float gv = g[(size_t)slot * CD + k];
        float uv = u[(size_t)slot * CD + k];
        float rl = fmaxf(gv, 0.f);
        float h = rl * rl * uv;
        hb[k] = h;
        amax = fmaxf(amax, fabsf(h));
    }
    amax = blk_reduce_max(amax, red);
    float m = fmaxf(amax, 1e-5f);
    float s = 127.f / m;
    #pragma unroll
    for (int i = 0; i < 4; i++) {
        int k = tid + i * 256;
        float qv = fminf(fmaxf(rintf(hb[k] * s), -128.f), 127.f);
        hq[(size_t)slot * CD + k] = (int8_t)(int)qv;
    }
    if (tid == 0) hs[slot] = m * (1.0f / 127.f);
}

// ---------------- launch (fork-join dual stream) ----------------
extern "C" void kernel_launch(void* const* d_in, const int* in_sizes, int n_in,
                              void* d_out, int out_size) {
    const float* x        = (const float*)d_in[0];
    const float* q_w      = (const float*)d_in[1];
    const float* k_w      = (const float*)d_in[2];
    const float* v_w      = (const float*)d_in[3];
    const float* o_w      = (const float*)d_in[4];
    const float* ln1_w    = (const float*)d_in[5];
    const float* ln2_w    = (const float*)d_in[6];
    const float* router_w = (const float*)d_in[7];
    const float* gate_w   = (const float*)d_in[8];
    const float* up_w     = (const float*)d_in[9];
    const float* down_w   = (const float*)d_in[10];

    unsigned char* base = nullptr;
    cudaGetSymbolAddress((void**)&base, g_scratch);

    int8_t* wq_attn = (int8_t*)(base + OFF_WQ_ATTN);
    int8_t* wq_gate = (int8_t*)(base + OFF_WQ_GATE);
    int8_t* wq_up   = (int8_t*)(base + OFF_WQ_UP);
    int8_t* wq_down = (int8_t*)(base + OFF_WQ_DOWN);
    float*  wsc     = (float*)(base + OFF_WSCALE);
    float*  part    = (float*)(base + OFF_PART);
    int8_t* xq1     = (int8_t*)(base + OFF_XQ1);
    float*  a1s     = (float*)(base + OFF_A1S);
    __nv_bfloat16* qkvb = (__nv_bfloat16*)(base + OFF_QKV);
    float*  hb      = (float*)(base + OFF_HB);
    int8_t* hqa     = (int8_t*)(base + OFF_HQA);
    float*  hsa     = (float*)(base + OFF_HSA);
    float*  x2      = (float*)(base + OFF_X2);
    int8_t* xq2     = (int8_t*)(base + OFF_XQ2);
    float*  a2s     = (float*)(base + OFF_A2S);
    int*    idx     = (int*)(base + OFF_IDX);
    int*    cnt     = (int*)(base + OFF_CNT);
    int*    seg     = (int*)(base + OFF_SEG);
    int*    cur     = (int*)(base + OFF_CUR);
    int*    tbl2    = (int*)(base + OFF_TBL2);
    int*    tbl3    = (int*)(base + OFF_TBL3);
    int*    perm    = (int*)(base + OFF_PERM);
    float*  gb      = (float*)(base + OFF_GB);
    float*  ub      = (float*)(base + OFF_UB);
    int8_t* hqm     = (int8_t*)(base + OFF_HQM);
    float*  hsm     = (float*)(base + OFF_HSM);
    float*  out     = (float*)d_out;

    const int LEN4 = (CH * CH) / 4;

    cudaStream_t s2;
    cudaStreamCreateWithFlags(&s2, cudaStreamNonBlocking);
    cudaEvent_t evFork, evB, evJoin;
    cudaEventCreateWithFlags(&evFork, cudaEventDisableTiming);
    cudaEventCreateWithFlags(&evB, cudaEventDisableTiming);
    cudaEventCreateWithFlags(&evJoin, cudaEventDisableTiming);

    cudaEventRecord(evFork, 0);
    cudaStreamWaitEvent(s2, evFork, 0);

    // ---- side stream: counter zeroing + activation quant + MoE weight quant ----
    zero_ints<<<1, 32, 0, s2>>>(cnt, cur);
    rmsnorm_quant<<<CT, 256, 0, s2>>>(x, ln1_w, xq1, a1s);
    cudaEventRecord(evB, s2);
    absmean_partial<<<dim3(256, 8), 256, 0, s2>>>(gate_w, part + 4 * 256, LEN4);
    absmean_partial<<<dim3(256, 8), 256, 0, s2>>>(up_w,   part + 12 * 256, LEN4);
    absmean_partial<<<dim3(256, 8), 256, 0, s2>>>(down_w, part + 20 * 256, LEN4);
    finalize_wscale<<<1, 32, 0, s2>>>(part, wsc, 4, 24);
    quantize_w<<<dim3(256, 8), 256, 0, s2>>>(gate_w, wq_gate, wsc, 4, LEN4);
    quantize_w<<<dim3(256, 8), 256, 0, s2>>>(up_w,   wq_up,   wsc, 12, LEN4);
    quantize_w<<<dim3(256, 8), 256, 0, s2>>>(down_w, wq_down, wsc, 20, LEN4);
    cudaEventRecord(evJoin, s2);

    // ---- main stream: attention weights + attention path ----
    absmean4<<<dim3(256, 4), 256>>>(q_w, k_w, v_w, o_w, part, LEN4);
    quantizeF4<<<dim3(256, 4), 256>>>(q_w, k_w, v_w, o_w, wq_attn, part, wsc, LEN4);
    cudaStreamWaitEvent(0, evB, 0);
    gemm_mma<0><<<dim3(16, 32, 3), 256>>>(xq1, wq_attn, nullptr, qkvb, a1s, wsc, nullptr, nullptr, nullptr, nullptr);

    attn_fa2<<<dim3(16, CB * CNH), 128>>>(
        qkvb, qkvb + (size_t)CT * CH, qkvb + 2 * (size_t)CT * CH, hb);

    // ---- o-proj + residual ----
    act_quant_rows<<<CT, 256>>>(hb, hqa, hsa);
    gemm_mma<1><<<dim3(16, 32, 1), 256>>>(hqa, wq_attn + 3 * (CH * CH), x2, nullptr, hsa, wsc + 3, x, nullptr, nullptr, nullptr);

    // ---- MoE ----
    rmsnorm2_router<<<CT, 256>>>(x2, ln2_w, router_w, xq2, a2s, idx, cnt);
    build_offsets<<<1, 1>>>(cnt, seg, tbl2, tbl3);
    scatter_tokens<<<16, 256>>>(idx, seg, cur, perm);

    cudaStreamWaitEvent(0, evJoin, 0);
    // compact tile grids: gate/up <= 80 tiles, down <= 40 tiles
    gemm_mma<2><<<dim3(16, 80), 256>>>(xq2, wq_gate, gb, nullptr, a2s, wsc + 4, nullptr, perm, seg, tbl2);
    hh_quant<<<CT, 256>>>(gb, ub, hqm, hsm);
    gemm_mma<3><<<dim3(16, 40), 256>>>(hqm, wq_down, out, nullptr, hsm, wsc + 20, x2, perm, seg, tbl3);
}

// round 17
// speedup vs baseline: 1.0172x; 1.0172x over previous
#include <cuda_runtime.h>
#include <cuda_bf16.h>
#include <math.h>
#include <stdint.h>

#define CB 2
#define CS 2048
#define CH 1024
#define CNH 16
#define CHD 64
#define CE 8
#define CD 1024
#define CT (CB*CS)

#define MB (1024ull*1024ull)

// ---------------- scratch layout ----------------
static constexpr size_t OFF_WQ_ATTN = 0;
static constexpr size_t OFF_WQ_GATE = 4*MB;
static constexpr size_t OFF_WQ_UP   = 12*MB;
static constexpr size_t OFF_WQ_DOWN = 20*MB;
static constexpr size_t OFF_WSCALE  = 28*MB;
static constexpr size_t OFF_PART    = 28*MB + 4096;
static constexpr size_t OFF_XQ1     = 29*MB;
static constexpr size_t OFF_A1S     = 33*MB;
static constexpr size_t OFF_QKV     = 34*MB;
static constexpr size_t OFF_HB      = 82*MB;
static constexpr size_t OFF_HQA     = 98*MB;
static constexpr size_t OFF_HSA     = 102*MB;
static constexpr size_t OFF_X2      = 103*MB;
static constexpr size_t OFF_XQ2     = 119*MB;
static constexpr size_t OFF_A2S     = 123*MB;
static constexpr size_t OFF_IDX     = 123*MB + 64*1024;
static constexpr size_t OFF_CNT     = 123*MB + 128*1024;
static constexpr size_t OFF_SEG     = 123*MB + 129*1024;
static constexpr size_t OFF_CUR     = 123*MB + 130*1024;
static constexpr size_t OFF_PERM    = 124*MB;
static constexpr size_t OFF_GB      = 125*MB;
static constexpr size_t OFF_UB      = 141*MB;
static constexpr size_t OFF_HQM     = 157*MB;
static constexpr size_t OFF_HSM     = 161*MB;
static constexpr size_t SCRATCH_BYTES = 162*MB;

__device__ __align__(256) unsigned char g_scratch[SCRATCH_BYTES];

// ---------------- reductions ----------------
__device__ __forceinline__ float blk_reduce_sum(float v, float* red) {
    int tid = threadIdx.x;
    red[tid] = v; __syncthreads();
    #pragma unroll
    for (int s = 128; s > 0; s >>= 1) {
        if (tid < s) red[tid] += red[tid + s];
        __syncthreads();
    }
    float r = red[0]; __syncthreads();
    return r;
}

__device__ __forceinline__ float blk_reduce_max(float v, float* red) {
    int tid = threadIdx.x;
    red[tid] = v; __syncthreads();
    #pragma unroll
    for (int s = 128; s > 0; s >>= 1) {
        if (tid < s) red[tid] = fmaxf(red[tid], red[tid + s]);
        __syncthreads();
    }
    float r = red[0]; __syncthreads();
    return r;
}

// ---------------- weight quantization (4x float4 ILP) ----------------
__device__ __forceinline__ float abs4(float4 v) {
    return fabsf(v.x) + fabsf(v.y) + fabsf(v.z) + fabsf(v.w);
}

__global__ void absmean_partial(const float* __restrict__ w, float* __restrict__ part, int len4) {
    __shared__ float red[256];
    const float4* p = (const float4*)w + (size_t)blockIdx.y * len4;
    int i = blockIdx.x * 1024 + threadIdx.x;
    float4 v0 = p[i], v1 = p[i + 256], v2 = p[i + 512], v3 = p[i + 768];
    float s = (abs4(v0) + abs4(v1)) + (abs4(v2) + abs4(v3));
    s = blk_reduce_sum(s, red);
    if (threadIdx.x == 0) part[(size_t)blockIdx.y * gridDim.x + blockIdx.x] = s;
}

__global__ void absmean4(const float* __restrict__ w0, const float* __restrict__ w1,
                         const float* __restrict__ w2, const float* __restrict__ w3,
                         float* __restrict__ part, int len4) {
    __shared__ float red[256];
    int sl = blockIdx.y;
    const float* p = sl == 0 ? w0 : sl == 1 ? w1 : sl == 2 ? w2 : w3;
    const float4* p4 = (const float4*)p;
    int i = blockIdx.x * 1024 + threadIdx.x;
    float4 v0 = p4[i], v1 = p4[i + 256], v2 = p4[i + 512], v3 = p4[i + 768];
    float s = (abs4(v0) + abs4(v1)) + (abs4(v2) + abs4(v3));
    s = blk_reduce_sum(s, red);
    if (threadIdx.x == 0) part[(size_t)sl * gridDim.x + blockIdx.x] = s;
}

__global__ void finalize_wscale(const float* __restrict__ part, float* __restrict__ wsc,
                                int i0, int n) {
    int i = i0 + threadIdx.x;
    if (threadIdx.x >= n) return;
    float s = 0.f;
    for (int j = 0; j < 256; j++) s += part[i * 256 + j];
    wsc[i] = fmaxf(s * (1.0f / (1024.f * 1024.f)), 1e-5f);
}

__device__ __forceinline__ char quant_tern(float v, float s) {
    float q = rintf(v * s);
    q = fminf(fmaxf(q, -1.f), 1.f);
    return (char)(int)q;
}

__device__ __forceinline__ char4 qt4(float4 v, float s) {
    char4 o;
    o.x = quant_tern(v.x, s); o.y = quant_tern(v.y, s);
    o.z = quant_tern(v.z, s); o.w = quant_tern(v.w, s);
    return o;
}

__global__ void quantize_w(const float* __restrict__ w, int8_t* __restrict__ wq,
                           const float* __restrict__ wsc, int widx0, int len4) {
    int slice = blockIdx.y;
    float s = 1.0f / wsc[widx0 + slice];
    const float4* p = (const float4*)w + (size_t)slice * len4;
    char4* q = (char4*)wq + (size_t)slice * len4;
    int i = blockIdx.x * 1024 + threadIdx.x;
    float4 v0 = p[i], v1 = p[i + 256], v2 = p[i + 512], v3 = p[i + 768];
    q[i] = qt4(v0, s); q[i + 256] = qt4(v1, s);
    q[i + 512] = qt4(v2, s); q[i + 768] = qt4(v3, s);
}

__global__ void quantizeF4(const float* __restrict__ w0, const float* __restrict__ w1,
                           const float* __restrict__ w2, const float* __restrict__ w3,
                           int8_t* __restrict__ wq, const float* __restrict__ part,
                           float* __restrict__ wsc, int len4) {
    __shared__ float red[256];
    int sl = blockIdx.y;
    int tid = threadIdx.x;
    float total = blk_reduce_sum(part[sl * 256 + tid], red);
    float mean = fmaxf(total * (1.0f / (1024.f * 1024.f)), 1e-5f);
    if (blockIdx.x == 0 && tid == 0) wsc[sl] = mean;
    float s = 1.0f / mean;
    const float* p = sl == 0 ? w0 : sl == 1 ? w1 : sl == 2 ? w2 : w3;
    const float4* p4 = (const float4*)p;
    char4* q = (char4*)wq + (size_t)sl * len4;
    int i = blockIdx.x * 1024 + tid;
    float4 v0 = p4[i], v1 = p4[i + 256], v2 = p4[i + 512], v3 = p4[i + 768];
    q[i] = qt4(v0, s); q[i + 256] = qt4(v1, s);
    q[i + 512] = qt4(v2, s); q[i + 768] = qt4(v3, s);
}

// ---------------- activation rmsnorm + quant ----------------
__global__ void rmsnorm_quant(const float* __restrict__ x, const float* __restrict__ lnw,
                              int8_t* __restrict__ xq, float* __restrict__ ainv) {
    __shared__ float red[256];
    __shared__ float xs[CH];
    int t = blockIdx.x, tid = threadIdx.x;
    const float* xr = x + (size_t)t * CH;
    float v[4]; float ss = 0.f;
    #pragma unroll
    for (int i = 0; i < 4; i++) { v[i] = xr[tid + i * 256]; ss += v[i] * v[i]; }
    ss = blk_reduce_sum(ss, red);
    float r = rsqrtf(ss * (1.0f / CH) + 1e-5f);
    float amax = 0.f;
    #pragma unroll
    for (int i = 0; i < 4; i++) {
        float xn = v[i] * r * lnw[tid + i * 256];
        xs[tid + i * 256] = xn;
        amax = fmaxf(amax, fabsf(xn));
    }
    amax = blk_reduce_max(amax, red);
    float m = fmaxf(amax, 1e-5f);
    float s = 127.f / m;
    #pragma unroll
    for (int i = 0; i < 4; i++) {
        float qv = fminf(fmaxf(rintf(xs[tid + i * 256] * s), -128.f), 127.f);
        xq[(size_t)t * CH + tid + i * 256] = (int8_t)(int)qv;
    }
    if (tid == 0) ainv[t] = m * (1.0f / 127.f);
}

__global__ void act_quant_rows(const float* __restrict__ x, int8_t* __restrict__ xq,
                               float* __restrict__ ainv) {
    __shared__ float red[256];
    int t = blockIdx.x, tid = threadIdx.x;
    const float* xr = x + (size_t)t * CH;
    float v[4]; float amax = 0.f;
    #pragma unroll
    for (int i = 0; i < 4; i++) { v[i] = xr[tid + i * 256]; amax = fmaxf(amax, fabsf(v[i])); }
    amax = blk_reduce_max(amax, red);
    float m = fmaxf(amax, 1e-5f);
    float s = 127.f / m;
    #pragma unroll
    for (int i = 0; i < 4; i++) {
        float qv = fminf(fmaxf(rintf(v[i] * s), -128.f), 127.f);
        xq[(size_t)t * CH + tid + i * 256] = (int8_t)(int)qv;
    }
    if (tid == 0) ainv[t] = m * (1.0f / 127.f);
}

__global__ void rmsnorm2_router(const float* __restrict__ x, const float* __restrict__ lnw,
                                const float* __restrict__ rw, int8_t* __restrict__ xq,
                                float* __restrict__ ainv, int* __restrict__ idx,
                                int* __restrict__ counts) {
    __shared__ float red[256];
    __shared__ float xs[CH];
    __shared__ float logits[CE];
    int t = blockIdx.x, tid = threadIdx.x;
    const float* xr = x + (size_t)t * CH;
    float v[4]; float ss = 0.f;
    #pragma unroll
    for (int i = 0; i < 4; i++) { v[i] = xr[tid + i * 256]; ss += v[i] * v[i]; }
    ss = blk_reduce_sum(ss, red);
    float r = rsqrtf(ss * (1.0f / CH) + 1e-5f);
    float amax = 0.f;
    #pragma unroll
    for (int i = 0; i < 4; i++) {
        float xn = v[i] * r * lnw[tid + i * 256];
        xs[tid + i * 256] = xn;
        amax = fmaxf(amax, fabsf(xn));
    }
    amax = blk_reduce_max(amax, red);
    float m = fmaxf(amax, 1e-5f);
    float s = 127.f / m;
    #pragma unroll
    for (int i = 0; i < 4; i++) {
        float qv = fminf(fmaxf(rintf(xs[tid + i * 256] * s), -128.f), 127.f);
        xq[(size_t)t * CH + tid + i * 256] = (int8_t)(int)qv;
    }
    if (tid == 0) ainv[t] = m * (1.0f / 127.f);
    __syncthreads();

    int w = tid >> 5, lane = tid & 31;
    float acc = 0.f;
    for (int h = lane; h < CH; h += 32) acc += xs[h] * rw[w * CH + h];
    #pragma unroll
    for (int o = 16; o > 0; o >>= 1) acc += __shfl_down_sync(0xffffffffu, acc, o);
    if (lane == 0) logits[w] = acc;
    __syncthreads();
    if (tid == 0) {
        float best = logits[0]; int bi = 0;
        #pragma unroll
        for (int e = 1; e < CE; e++) if (logits[e] > best) { best = logits[e]; bi = e; }
        idx[t] = bi;
        atomicAdd(&counts[bi], 1);
    }
}

__global__ void zero_ints(int* __restrict__ counts, int* __restrict__ cursor) {
    if (threadIdx.x < CE) { counts[threadIdx.x] = 0; cursor[threadIdx.x] = 0; }
}

__global__ void build_offsets(const int* __restrict__ counts, int* __restrict__ seg) {
    if (threadIdx.x == 0) {
        int a = 0;
        for (int e = 0; e < CE; e++) { seg[e] = a; a += counts[e]; }
        seg[CE] = a;
    }
}

__global__ void scatter_tokens(const int* __restrict__ idx, const int* __restrict__ seg,
                               int* __restrict__ cursor, int* __restrict__ perm) {
    int t = blockIdx.x * 256 + threadIdx.x;
    if (t >= CT) return;
    int e = idx[t];
    int p = atomicAdd(&cursor[e], 1);
    perm[seg[e] + p] = t;
}

// ---------------- int8 x ternary GEMM: mma.sync + ldmatrix + cp.async (3-stage) ----------------
__device__ __forceinline__ void mma_s8(int* c, const int* a, const int* b) {
    asm volatile(
        "mma.sync.aligned.m16n8k32.row.col.s32.s8.s8.s32 "
        "{%0,%1,%2,%3}, {%4,%5,%6,%7}, {%8,%9}, {%0,%1,%2,%3};"
        : "+r"(c[0]), "+r"(c[1]), "+r"(c[2]), "+r"(c[3])
        : "r"(a[0]), "r"(a[1]), "r"(a[2]), "r"(a[3]), "r"(b[0]), "r"(b[1]));
}

#define LDMX4(r, addr) \
    asm volatile("ldmatrix.sync.aligned.m8n8.x4.shared.b16 {%0,%1,%2,%3}, [%4];" \
        : "=r"((r)[0]), "=r"((r)[1]), "=r"((r)[2]), "=r"((r)[3]) : "r"(addr))

#define CPA16(dst, src) \
    asm volatile("cp.async.cg.shared.global [%0], [%1], 16;" :: "r"(dst), "l"(src))
#define CPCOMMIT() asm volatile("cp.async.commit_group;" ::: "memory")

static constexpr int A_STG = 128 * 80;
static constexpr int B_STG = 64 * 80;

template<int MODE>
__global__ void __launch_bounds__(256) gemm_mma(
        const int8_t* __restrict__ A, const int8_t* __restrict__ Bw,
        float* __restrict__ Out, __nv_bfloat16* __restrict__ OutB,
        const float* __restrict__ ascale,
        const float* __restrict__ wscale,
        const float* __restrict__ resid,
        const int* __restrict__ perm,
        const int* __restrict__ seg) {
    int n0 = blockIdx.x * 64;
    int m0 = blockIdx.y * 128;
    int z = blockIdx.z;
    int e = (MODE == 2) ? (z & 7) : z;

    int off = 0, cnt = CT;
    if (MODE >= 2) {
        off = seg[e];
        cnt = seg[e + 1] - off;
        if (m0 >= cnt) return;
    }

    const int8_t* Bz = Bw;
    if (MODE == 0) Bz = Bw + (size_t)z * (CH * CH);
    if (MODE >= 2) Bz = Bw + (size_t)z * ((size_t)CD * CH);
    const int8_t* brow0 = Bz + (size_t)n0 * 1024;

    __shared__ __align__(16) int8_t As[3][128][80];
    __shared__ __align__(16) int8_t Bs[3][64][80];
    __shared__ const int8_t* aptr[128];
    __shared__ float rowsc[128];
    __shared__ int dstrow[128];

    int tid = threadIdx.x;
    if (tid < 128) {
        int r = m0 + tid;
        if (MODE <= 1) {
            aptr[tid] = A + (size_t)r * 1024;
            rowsc[tid] = ascale[r];
        } else if (MODE == 2) {
            int rr = r < cnt - 1 ? r : cnt - 1;
            int tok = perm[off + rr];
            aptr[tid] = A + (size_t)tok * 1024;
            rowsc[tid] = ascale[tok];
            dstrow[tid] = off + r;
        } else {
            int rr = r < cnt - 1 ? r : cnt - 1;
            aptr[tid] = A + (size_t)(off + rr) * 1024;
            rowsc[tid] = ascale[off + rr];
            dstrow[tid] = perm[off + rr];
        }
    }
    __syncthreads();

    int ar = tid >> 1, ao = (tid & 1) * 32;
    int brr = tid >> 2, bo = (tid & 3) * 16;
    const int8_t* pA = aptr[ar];
    const int8_t* pB = brow0 + (size_t)brr * 1024;

    uint32_t As_u = (uint32_t)__cvta_generic_to_shared(&As[0][0][0]);
    uint32_t Bs_u = (uint32_t)__cvta_generic_to_shared(&Bs[0][0][0]);
    uint32_t aSt = As_u + ar * 80 + ao;
    uint32_t bSt = Bs_u + brr * 80 + bo;

    int w = tid >> 5, lane = tid & 31;
    int warpM = w & 3, warpN = w >> 2;
    int gid = lane >> 2, tig = lane & 3;

    int rowA_ld = warpM * 32 + (lane & 7) + ((lane >> 3) & 1) * 8;
    uint32_t aF = As_u + rowA_ld * 80 + (lane >> 4) * 16;
    int rowB_ld = warpN * 32 + (lane & 7) + (lane >> 4) * 8;
    uint32_t bF = Bs_u + rowB_ld * 80 + ((lane >> 3) & 1) * 16;

    int c[2][4][4];
    #pragma unroll
    for (int i = 0; i < 2; i++)
        #pragma unroll
        for (int j = 0; j < 4; j++)
            #pragma unroll
            for (int k = 0; k < 4; k++) c[i][j][k] = 0;

    #pragma unroll
    for (int s = 0; s < 2; s++) {
        uint32_t aD = aSt + s * A_STG;
        CPA16(aD, pA + s * 64 + ao);
        CPA16(aD + 16, pA + s * 64 + ao + 16);
        CPA16(bSt + s * B_STG, pB + s * 64 + bo);
        CPCOMMIT();
    }

    #pragma unroll 1
    for (int kt = 0; kt < 16; kt++) {
        if (kt < 15) {
            asm volatile("cp.async.wait_group 1;" ::: "memory");
        } else {
            asm volatile("cp.async.wait_group 0;" ::: "memory");
        }
        // head barrier: (a) makes all threads' cp.async for the current stage
        // visible, (b) proves everyone finished computing on the buffer the
        // next prefetch below will overwrite — tail barrier is redundant.
        __syncthreads();
        if (kt < 14) {
            int s = kt + 2;
            int b = s % 3;
            uint32_t aD = aSt + b * A_STG;
            CPA16(aD, pA + s * 64 + ao);
            CPA16(aD + 16, pA + s * 64 + ao + 16);
            CPA16(bSt + b * B_STG, pB + s * 64 + bo);
            CPCOMMIT();
        }
        int stg = kt % 3;
        uint32_t aBase = aF + stg * A_STG;
        uint32_t bBase = bF + stg * B_STG;
        #pragma unroll
        for (int ks = 0; ks < 2; ks++) {
            int a0[4], a1[4], b01[4], b23[4];
            LDMX4(a0, aBase + ks * 32);
            LDMX4(a1, aBase + 16 * 80 + ks * 32);
            LDMX4(b01, bBase + ks * 32);
            LDMX4(b23, bBase + 16 * 80 + ks * 32);
            mma_s8(c[0][0], a0, b01 + 0);
            mma_s8(c[0][1], a0, b01 + 2);
            mma_s8(c[0][2], a0, b23 + 0);
            mma_s8(c[0][3], a0, b23 + 2);
            mma_s8(c[1][0], a1, b01 + 0);
            mma_s8(c[1][1], a1, b01 + 2);
            mma_s8(c[1][2], a1, b23 + 0);
            mma_s8(c[1][3], a1, b23 + 2);
        }
    }

    float wS = wscale[(MODE == 0 || MODE >= 2) ? z : 0];

    #pragma unroll
    for (int wm = 0; wm < 2; wm++) {
        int r0 = warpM * 32 + wm * 16 + gid;
        int r1 = r0 + 8;
        float av0 = rowsc[r0] * wS;
        float av1 = rowsc[r1] * wS;
        #pragma unroll
        for (int nt = 0; nt < 4; nt++) {
            int colL = warpN * 32 + nt * 8 + tig * 2;
            int* cc = c[wm][nt];
            if (MODE == 0) {
                int nh = n0 >> 6;
                int gr0 = m0 + r0, gr1 = m0 + r1;
                int b0 = gr0 / CS, sr0 = gr0 % CS;
                int b1 = gr1 / CS, sr1 = gr1 % CS;
                __nv_bfloat16* base = OutB + (size_t)z * ((size_t)CT * CH);
                __nv_bfloat162 o0 = {__float2bfloat16(cc[0] * av0), __float2bfloat16(cc[1] * av0)};
                __nv_bfloat162 o1 = {__float2bfloat16(cc[2] * av1), __float2bfloat16(cc[3] * av1)};
                *(__nv_bfloat162*)(base + (((size_t)b0 * CNH + nh) * CS + sr0) * CHD + colL) = o0;
                *(__nv_bfloat162*)(base + (((size_t)b1 * CNH + nh) * CS + sr1) * CHD + colL) = o1;
            } else if (MODE == 1) {
                size_t rb0 = (size_t)(m0 + r0) * CH + n0 + colL;
                size_t rb1 = (size_t)(m0 + r1) * CH + n0 + colL;
                float2 rv0 = *(const float2*)(resid + rb0);
                float2 rv1 = *(const float2*)(resid + rb1);
                float2 o0 = {rv0.x + cc[0] * av0, rv0.y + cc[1] * av0};
                float2 o1 = {rv1.x + cc[2] * av1, rv1.y + cc[3] * av1};
                *(float2*)(Out + rb0) = o0;
                *(float2*)(Out + rb1) = o1;
            } else if (MODE == 2) {
                size_t half = (size_t)(z >> 3) * ((size_t)CT * CD);
                if (m0 + r0 < cnt) {
                    size_t rb = half + (size_t)dstrow[r0] * CD + n0 + colL;
                    float2 o = {cc[0] * av0, cc[1] * av0};
                    *(float2*)(Out + rb) = o;
                }
                if (m0 + r1 < cnt) {
                    size_t rb = half + (size_t)dstrow[r1] * CD + n0 + colL;
                    float2 o = {cc[2] * av1, cc[3] * av1};
                    *(float2*)(Out + rb) = o;
                }
            } else {
                if (m0 + r0 < cnt) {
                    size_t rb = (size_t)dstrow[r0] * CH + n0 + colL;
                    float2 rv = *(const float2*)(resid + rb);
                    float2 o = {rv.x + cc[0] * av0, rv.y + cc[1] * av0};
                    *(float2*)(Out + rb) = o;
                }
                if (m0 + r1 < cnt) {
                    size_t rb = (size_t)dstrow[r1] * CH + n0 + colL;
                    float2 rv = *(const float2*)(resid + rb);
                    float2 o = {rv.x + cc[2] * av1, rv.y + cc[3] * av1};
                    *(float2*)(Out + rb) = o;
                }
            }
        }
    }
}

// ---------------- attention: FA2-style, causal-balanced, cp.async double-buffered K/V ----------------
__device__ __forceinline__ void mma_bf16(float* c, const uint32_t* a, uint32_t b0, uint32_t b1) {
    asm volatile(
        "mma.sync.aligned.m16n8k16.row.col.f32.bf16.bf16.f32 "
        "{%0,%1,%2,%3}, {%4,%5,%6,%7}, {%8,%9}, {%0,%1,%2,%3};"
        : "+f"(c[0]), "+f"(c[1]), "+f"(c[2]), "+f"(c[3])
        : "r"(a[0]), "r"(a[1]), "r"(a[2]), "r"(a[3]), "r"(b0), "r"(b1));
}

__device__ __forceinline__ void ldmx4t(uint32_t& r0, uint32_t& r1, uint32_t& r2, uint32_t& r3,
                                       uint32_t addr) {
    asm volatile("ldmatrix.sync.aligned.m8n8.x4.trans.shared.b16 {%0,%1,%2,%3}, [%4];"
        : "=r"(r0), "=r"(r1), "=r"(r2), "=r"(r3) : "r"(addr));
}

__device__ __forceinline__ uint32_t pack_bf2(float a, float b) {
    __nv_bfloat162 t = __floats2bfloat162_rn(a, b);
    return *(uint32_t*)&t;
}

static constexpr int KLD = 72;
#define ASCL 0.18033688011112042f   // 0.125 * log2(e)

__global__ void __launch_bounds__(128) attn_fa2(
        const __nv_bfloat16* __restrict__ Qg, const __nv_bfloat16* __restrict__ Kg,
        const __nv_bfloat16* __restrict__ Vg, float* __restrict__ Hout) {
    __shared__ __align__(16) __nv_bfloat16 Ks[2][64][KLD];
    __shared__ __align__(16) __nv_bfloat16 Vs[2][64][KLD];

    int bh = blockIdx.y;
    const __nv_bfloat16* Qb = Qg + (size_t)bh * CS * CHD;
    const __nv_bfloat16* Kb = Kg + (size_t)bh * CS * CHD;
    const __nv_bfloat16* Vb = Vg + (size_t)bh * CS * CHD;

    int tid = threadIdx.x;
    int w = tid >> 5, lane = tid & 31;
    int gid = lane >> 2, tig = lane & 3;

    int b = bh / CNH, nh = bh % CNH;

    int lrow[4], lcol[4];
    #pragma unroll
    for (int u = 0; u < 4; u++) {
        int i = tid + u * 128;
        lrow[u] = i >> 3;
        lcol[u] = (i & 7) * 8;
    }

    #pragma unroll 1
    for (int rep = 0; rep < 2; rep++) {
        int qb = rep == 0 ? (31 - (int)blockIdx.x) : (int)blockIdx.x;
        int q0 = qb * 64;
        int qr0 = q0 + w * 16 + gid;
        int qr1 = qr0 + 8;

        uint32_t qf[4][4];
        #pragma unroll
        for (int k = 0; k < 4; k++) {
            const __nv_bfloat16* p0 = Qb + (size_t)qr0 * CHD + k * 16 + 2 * tig;
            const __nv_bfloat16* p1 = Qb + (size_t)qr1 * CHD + k * 16 + 2 * tig;
            qf[k][0] = *(const uint32_t*)p0;
            qf[k][1] = *(const uint32_t*)p1;
            qf[k][2] = *(const uint32_t*)(p0 + 8);
            qf[k][3] = *(const uint32_t*)(p1 + 8);
        }

        float o[8][4];
        #pragma unroll
        for (int nt = 0; nt < 8; nt++)
            #pragma unroll
            for (int j = 0; j < 4; j++) o[nt][j] = 0.f;
        float m0 = -INFINITY, m1 = -INFINITY, l0 = 0.f, l1 = 0.f;

        int nkt = qb + 1;

        __syncthreads();
        #pragma unroll
        for (int u = 0; u < 4; u++) {
            CPA16((uint32_t)__cvta_generic_to_shared(&Ks[0][lrow[u]][lcol[u]]),
                  Kb + (size_t)lrow[u] * CHD + lcol[u]);
            CPA16((uint32_t)__cvta_generic_to_shared(&Vs[0][lrow[u]][lcol[u]]),
                  Vb + (size_t)lrow[u] * CHD + lcol[u]);
        }
        CPCOMMIT();

        #pragma unroll 1
        for (int kt = 0; kt < nkt; kt++) {
            int buf = kt & 1;
            asm volatile("cp.async.wait_group 0;" ::: "memory");
            __syncthreads();
            if (kt + 1 < nkt) {
                int k0n = (kt + 1) * 64;
                int nb = buf ^ 1;
                #pragma unroll
                for (int u = 0; u < 4; u++) {
                    CPA16((uint32_t)__cvta_generic_to_shared(&Ks[nb][lrow[u]][lcol[u]]),
                          Kb + (size_t)(k0n + lrow[u]) * CHD + lcol[u]);
                    CPA16((uint32_t)__cvta_generic_to_shared(&Vs[nb][lrow[u]][lcol[u]]),
                          Vb + (size_t)(k0n + lrow[u]) * CHD + lcol[u]);
                }
                CPCOMMIT();
            }
            int k0 = kt * 64;

            float s[8][4];
            #pragma unroll
            for (int nt = 0; nt < 8; nt++)
                #pragma unroll
                for (int j = 0; j < 4; j++) s[nt][j] = 0.f;
            #pragma unroll
            for (int k = 0; k < 4; k++) {
                #pragma unroll
                for (int nt = 0; nt < 8; nt++) {
                    uint32_t b0 = *(const uint32_t*)&Ks[buf][nt * 8 + gid][k * 16 + 2 * tig];
                    uint32_t b1 = *(const uint32_t*)&Ks[buf][nt * 8 + gid][k * 16 + 8 + 2 * tig];
                    mma_bf16(s[nt], qf[k], b0, b1);
                }
            }

            bool diag = (kt == qb);
            float rmax0 = -INFINITY, rmax1 = -INFINITY;
            #pragma unroll
            for (int nt = 0; nt < 8; nt++) {
                int cg = k0 + nt * 8 + 2 * tig;
                #pragma unroll
                for (int j = 0; j < 2; j++) {
                    float v0 = s[nt][j] * ASCL;
                    float v1 = s[nt][2 + j] * ASCL;
                    if (diag && cg + j > qr0) v0 = -INFINITY;
                    if (diag && cg + j > qr1) v1 = -INFINITY;
                    s[nt][j] = v0; s[nt][2 + j] = v1;
                    rmax0 = fmaxf(rmax0, v0); rmax1 = fmaxf(rmax1, v1);
                }
            }
            rmax0 = fmaxf(rmax0, __shfl_xor_sync(0xffffffffu, rmax0, 1));
            rmax0 = fmaxf(rmax0, __shfl_xor_sync(0xffffffffu, rmax0, 2));
            rmax1 = fmaxf(rmax1, __shfl_xor_sync(0xffffffffu, rmax1, 1));
            rmax1 = fmaxf(rmax1, __shfl_xor_sync(0xffffffffu, rmax1, 2));

            float mn0 = fmaxf(m0, rmax0), mn1 = fmaxf(m1, rmax1);
            float sum0 = 0.f, sum1 = 0.f;
            #pragma unroll
            for (int nt = 0; nt < 8; nt++) {
                s[nt][0] = exp2f(s[nt][0] - mn0);
                s[nt][1] = exp2f(s[nt][1] - mn0);
                s[nt][2] = exp2f(s[nt][2] - mn1);
                s[nt][3] = exp2f(s[nt][3] - mn1);
                sum0 += s[nt][0] + s[nt][1];
                sum1 += s[nt][2] + s[nt][3];
            }
            sum0 += __shfl_xor_sync(0xffffffffu, sum0, 1);
            sum0 += __shfl_xor_sync(0xffffffffu, sum0, 2);
            sum1 += __shfl_xor_sync(0xffffffffu, sum1, 1);
            sum1 += __shfl_xor_sync(0xffffffffu, sum1, 2);

            float rs0 = exp2f(m0 - mn0), rs1 = exp2f(m1 - mn1);
            m0 = mn0; m1 = mn1;
            l0 = l0 * rs0 + sum0;
            l1 = l1 * rs1 + sum1;
            #pragma unroll
            for (int nt = 0; nt < 8; nt++) {
                o[nt][0] *= rs0; o[nt][1] *= rs0;
                o[nt][2] *= rs1; o[nt][3] *= rs1;
            }

            #pragma unroll
            for (int kb = 0; kb < 4; kb++) {
                uint32_t pf[4];
                pf[0] = pack_bf2(s[2 * kb][0], s[2 * kb][1]);
                pf[1] = pack_bf2(s[2 * kb][2], s[2 * kb][3]);
                pf[2] = pack_bf2(s[2 * kb + 1][0], s[2 * kb + 1][1]);
                pf[3] = pack_bf2(s[2 * kb + 1][2], s[2 * kb + 1][3]);
                #pragma unroll
                for (int nb = 0; nb < 4; nb++) {
                    uint32_t v0, v1, v2, v3;
                    uint32_t addr = (uint32_t)__cvta_generic_to_shared(
                        &Vs[buf][kb * 16 + (lane & 15)][nb * 16 + ((lane >> 4) << 3)]);
                    ldmx4t(v0, v1, v2, v3, addr);
                    mma_bf16(o[2 * nb], pf, v0, v1);
                    mma_bf16(o[2 * nb + 1], pf, v2, v3);
                }
            }
        }

        float inv0 = 1.0f / l0, inv1 = 1.0f / l1;
        #pragma unroll
        for (int nt = 0; nt < 8; nt++) {
            int col = nt * 8 + 2 * tig;
            float2 w0v = {o[nt][0] * inv0, o[nt][1] * inv0};
            float2 w1v = {o[nt][2] * inv1, o[nt][3] * inv1};
            *(float2*)(Hout + (((size_t)b * CS + qr0) * CNH + nh) * CHD + col) = w0v;
            *(float2*)(Hout + (((size_t)b * CS + qr1) * CNH + nh) * CHD + col) = w1v;
        }
    }
}

// ---------------- MoE elementwise: hh = relu(g)^2 * u, then act_quant ----------------
__global__ void hh_quant(const float* __restrict__ g, const float* __restrict__ u,
                         int8_t* __restrict__ hq, float* __restrict__ hs) {
    __shared__ float red[256];
    __shared__ float hb[CD];
    int slot = blockIdx.x, tid = threadIdx.x;
    float amax = 0.f;
    #pragma unroll
    for (int i = 0; i < 4; i++) {
        int k = tid + i * 256;
        float gv = g[(size_t)slot * CD + k];
        float uv = u[(size_t)slot * CD + k];
        float rl = fmaxf(gv, 0.f);
        float h = rl * rl * uv;
        hb[k] = h;
        amax = fmaxf(amax, fabsf(h));
    }
    amax = blk_reduce_max(amax, red);
    float m = fmaxf(amax, 1e-5f);
    float s = 127.f / m;
    #pragma unroll
    for (int i = 0; i < 4; i++) {
        int k = tid + i * 256;
        float qv = fminf(fmaxf(rintf(hb[k] * s), -128.f), 127.f);
        hq[(size_t)slot * CD + k] = (int8_t)(int)qv;
    }
    if (tid == 0) hs[slot] = m * (1.0f / 127.f);
}

// ---------------- launch (fork-join dual stream) ----------------
extern "C" void kernel_launch(void* const* d_in, const int* in_sizes, int n_in,
                              void* d_out, int out_size) {
    const float* x        = (const float*)d_in[0];
    const float* q_w      = (const float*)d_in[1];
    const float* k_w      = (const float*)d_in[2];
    const float* v_w      = (const float*)d_in[3];
    const float* o_w      = (const float*)d_in[4];
    const float* ln1_w    = (const float*)d_in[5];
    const float* ln2_w    = (const float*)d_in[6];
    const float* router_w = (const float*)d_in[7];
    const float* gate_w   = (const float*)d_in[8];
    const float* up_w     = (const float*)d_in[9];
    const float* down_w   = (const float*)d_in[10];

    unsigned char* base = nullptr;
    cudaGetSymbolAddress((void**)&base, g_scratch);

    int8_t* wq_attn = (int8_t*)(base + OFF_WQ_ATTN);
    int8_t* wq_gate = (int8_t*)(base + OFF_WQ_GATE);
    int8_t* wq_up   = (int8_t*)(base + OFF_WQ_UP);
    int8_t* wq_down = (int8_t*)(base + OFF_WQ_DOWN);
    float*  wsc     = (float*)(base + OFF_WSCALE);
    float*  part    = (float*)(base + OFF_PART);
    int8_t* xq1     = (int8_t*)(base + OFF_XQ1);
    float*  a1s     = (float*)(base + OFF_A1S);
    __nv_bfloat16* qkvb = (__nv_bfloat16*)(base + OFF_QKV);
    float*  hb      = (float*)(base + OFF_HB);
    int8_t* hqa     = (int8_t*)(base + OFF_HQA);
    float*  hsa     = (float*)(base + OFF_HSA);
    float*  x2      = (float*)(base + OFF_X2);
    int8_t* xq2     = (int8_t*)(base + OFF_XQ2);
    float*  a2s     = (float*)(base + OFF_A2S);
    int*    idx     = (int*)(base + OFF_IDX);
    int*    cnt     = (int*)(base + OFF_CNT);
    int*    seg     = (int*)(base + OFF_SEG);
    int*    cur     = (int*)(base + OFF_CUR);
    int*    perm    = (int*)(base + OFF_PERM);
    float*  gb      = (float*)(base + OFF_GB);
    float*  ub      = (float*)(base + OFF_UB);
    int8_t* hqm     = (int8_t*)(base + OFF_HQM);
    float*  hsm     = (float*)(base + OFF_HSM);
    float*  out     = (float*)d_out;

    const int LEN4 = (CH * CH) / 4;

    cudaStream_t s2;
    cudaStreamCreateWithFlags(&s2, cudaStreamNonBlocking);
    cudaEvent_t evFork, evB, evJoin;
    cudaEventCreateWithFlags(&evFork, cudaEventDisableTiming);
    cudaEventCreateWithFlags(&evB, cudaEventDisableTiming);
    cudaEventCreateWithFlags(&evJoin, cudaEventDisableTiming);

    cudaEventRecord(evFork, 0);
    cudaStreamWaitEvent(s2, evFork, 0);

    // ---- side stream: counter zeroing + activation quant + MoE weight quant ----
    // zero_ints ordering to rmsnorm2_router is transitive: zero -> rmsnorm_quant
    // -> evB -> (main waits) gemm<0> -> ... -> router.
    zero_ints<<<1, 32, 0, s2>>>(cnt, cur);
    rmsnorm_quant<<<CT, 256, 0, s2>>>(x, ln1_w, xq1, a1s);
    cudaEventRecord(evB, s2);
    absmean_partial<<<dim3(256, 8), 256, 0, s2>>>(gate_w, part + 4 * 256, LEN4);
    absmean_partial<<<dim3(256, 8), 256, 0, s2>>>(up_w,   part + 12 * 256, LEN4);
    absmean_partial<<<dim3(256, 8), 256, 0, s2>>>(down_w, part + 20 * 256, LEN4);
    finalize_wscale<<<1, 32, 0, s2>>>(part, wsc, 4, 24);
    quantize_w<<<dim3(256, 8), 256, 0, s2>>>(gate_w, wq_gate, wsc, 4, LEN4);
    quantize_w<<<dim3(256, 8), 256, 0, s2>>>(up_w,   wq_up,   wsc, 12, LEN4);
    quantize_w<<<dim3(256, 8), 256, 0, s2>>>(down_w, wq_down, wsc, 20, LEN4);
    cudaEventRecord(evJoin, s2);

    // ---- main stream: attention weights + attention path ----
    absmean4<<<dim3(256, 4), 256>>>(q_w, k_w, v_w, o_w, part, LEN4);
    quantizeF4<<<dim3(256, 4), 256>>>(q_w, k_w, v_w, o_w, wq_attn, part, wsc, LEN4);
    cudaStreamWaitEvent(0, evB, 0);
    gemm_mma<0><<<dim3(16, 32, 3), 256>>>(xq1, wq_attn, nullptr, qkvb, a1s, wsc, nullptr, nullptr, nullptr);

    attn_fa2<<<dim3(16, CB * CNH), 128>>>(
        qkvb, qkvb + (size_t)CT * CH, qkvb + 2 * (size_t)CT * CH, hb);

    // ---- o-proj + residual ----
    act_quant_rows<<<CT, 256>>>(hb, hqa, hsa);
    gemm_mma<1><<<dim3(16, 32, 1), 256>>>(hqa, wq_attn + 3 * (CH * CH), x2, nullptr, hsa, wsc + 3, x, nullptr, nullptr);

    // ---- MoE ----
    rmsnorm2_router<<<CT, 256>>>(x2, ln2_w, router_w, xq2, a2s, idx, cnt);
    build_offsets<<<1, 1>>>(cnt, seg);
    scatter_tokens<<<16, 256>>>(idx, seg, cur, perm);

    cudaStreamWaitEvent(0, evJoin, 0);
    gemm_mma<2><<<dim3(16, 32, 16), 256>>>(xq2, wq_gate, gb, nullptr, a2s, wsc + 4, nullptr, perm, seg);
    hh_quant<<<CT, 256>>>(gb, ub, hqm, hsm);
    gemm_mma<3><<<dim3(16, 32, 8), 256>>>(hqm, wq_down, out, nullptr, hsm, wsc + 20, x2, perm, seg);
}